// round 7
// baseline (speedup 1.0000x reference)
#include <cuda_runtime.h>
#include <cuda_fp16.h>

#define M_Q   1024
#define N_T   8192
#define CDIM  256
#define OT_ITERS 1000
#define MARGIN_V 0.7f
#define NBLK 256
#define NTHR 256

// Static scratch (no runtime allocation allowed)
__device__ float  g_K[M_Q * N_T];     // fp32 kernel matrix (32 MB, L2-resident)
__device__ float  g_a[M_Q];
__device__ float  g_b[N_T];
__device__ float  g_t[N_T];
__device__ float  g_rmax[M_Q];
__device__ float  g_cmax[N_T];
__device__ float  g_R[M_Q * CDIM];
__device__ float  g_rn[M_Q];
__device__ float  g_s;                // Smu/Snu  (per-iter scale folded into nu)
__device__ float  g_inv_s;            // Snu/Smu  (epilogue correction)
__device__ volatile unsigned g_flags[NBLK];   // flag-array grid barrier

// Flag-array grid barrier: volatile spin (guaranteed re-load each poll).
// Each block publishes its epoch; each of the 256 threads polls one peer flag.
// Release: __threadfence before flag store. Acquire: __threadfence after spin.
__device__ __forceinline__ void grid_bar(unsigned ep) {
    __syncthreads();
    if (threadIdx.x == 0) {
        __threadfence();
        g_flags[blockIdx.x] = ep;
    }
    while (g_flags[threadIdx.x] < ep) __nanosleep(32);
    __threadfence();
    __syncthreads();
}

// ---------------------------------------------------------------------------
// t_j = sum_c T[j][c]^2
__global__ void k_t(const float* __restrict__ x) {
    int j = blockIdx.x * blockDim.x + threadIdx.x;
    int img = j >> 10, p = j & 1023;
    const float* base = x + (size_t)(img + 1) * CDIM * 1024 + p;
    float s = 0.f;
#pragma unroll 8
    for (int c = 0; c < CDIM; c++) { float v = base[c * 1024]; s += v * v; }
    g_t[j] = s;
}

// D[i][j] = t_j - 2 * sum_c Q[i][c]*T[j][c]   (fp32, into g_K)
__global__ void k_gemm(const float* __restrict__ x) {
    __shared__ float As[16][64];
    __shared__ float Bs[16][64];
    int i0 = blockIdx.y * 64;
    int j0 = blockIdx.x * 64;
    int img = j0 >> 10, p0 = j0 & 1023;
    const float* A = x;
    const float* B = x + (size_t)(img + 1) * CDIM * 1024;
    int tx = threadIdx.x, ty = threadIdx.y;
    int t = ty * 16 + tx;
    float acc[4][4] = {};
    for (int k0 = 0; k0 < CDIM; k0 += 16) {
#pragma unroll
        for (int s = 0; s < 4; s++) {
            int e = t + s * 256;
            int cl = e >> 6, il = e & 63;
            As[cl][il] = A[(size_t)(k0 + cl) * 1024 + i0 + il];
            Bs[cl][il] = B[(size_t)(k0 + cl) * 1024 + p0 + il];
        }
        __syncthreads();
#pragma unroll
        for (int c = 0; c < 16; c++) {
            float ra[4], rb[4];
#pragma unroll
            for (int u = 0; u < 4; u++) ra[u] = As[c][ty * 4 + u];
#pragma unroll
            for (int v = 0; v < 4; v++) rb[v] = Bs[c][tx * 4 + v];
#pragma unroll
            for (int u = 0; u < 4; u++)
#pragma unroll
                for (int v = 0; v < 4; v++) acc[u][v] += ra[u] * rb[v];
        }
        __syncthreads();
    }
#pragma unroll
    for (int u = 0; u < 4; u++) {
        int i = i0 + ty * 4 + u;
#pragma unroll
        for (int v = 0; v < 4; v++) {
            int j = j0 + tx * 4 + v;
            g_K[(size_t)i * N_T + j] = g_t[j] - 2.f * acc[u][v];
        }
    }
}

__global__ void k_rmax() {
    int i = blockIdx.x;
    const float* row = g_K + (size_t)i * N_T;
    int tid = threadIdx.x;
    float m = -1e30f;
    for (int j = tid; j < N_T; j += 256) m = fmaxf(m, row[j]);
    __shared__ float sm[256];
    sm[tid] = m; __syncthreads();
    for (int s = 128; s > 0; s >>= 1) {
        if (tid < s) sm[tid] = fmaxf(sm[tid], sm[tid + s]);
        __syncthreads();
    }
    if (tid == 0) g_rmax[i] = sm[0];
}

__global__ void k_cmax() {
    int j = blockIdx.x * 256 + threadIdx.x;
    float m = -1e30f;
    for (int i = 0; i < M_Q; i++)
        m = fmaxf(m, g_K[(size_t)i * N_T + j] - g_rmax[i]);
    g_cmax[j] = m;
}

// K = exp(D - rmax_i - cmax_j) in place (fp32 — R4-proven numerics).
// All entries in [0,1]; every row AND column has an exact 1.0.
__global__ void k_exp() {
    int i = blockIdx.x;
    float* row = g_K + (size_t)i * N_T;
    float rm = g_rmax[i];
    for (int j = threadIdx.x; j < N_T; j += 256)
        row[j] = __expf(row[j] - rm - g_cmax[j]);
}

// Marginal sums -> per-iteration scale s = Smu/Snu (kills geometric drift;
// exact: final plan is s*P, corrected by inv_s in the epilogue)
__global__ void k_sums(const float* __restrict__ att) {
    __shared__ float sm[256];
    int tid = threadIdx.x;
    float s1 = 0.f;
    for (int i = tid; i < M_Q; i += 256) s1 += att[i];
    sm[tid] = s1; __syncthreads();
    for (int s = 128; s > 0; s >>= 1) { if (tid < s) sm[tid] += sm[tid + s]; __syncthreads(); }
    float smu = sm[0]; __syncthreads();
    float s2 = 0.f;
    for (int j = tid; j < N_T; j += 256) s2 += att[M_Q + j];
    sm[tid] = s2; __syncthreads();
    for (int s = 128; s > 0; s >>= 1) { if (tid < s) sm[tid] += sm[tid + s]; __syncthreads(); }
    if (tid == 0) { g_s = smu / sm[0]; g_inv_s = sm[0] / smu; }
}

// b_0 = exp(cmax_j)  (== reference v=0 start); reset barrier flags (must be
// re-zeroed every launch: graph replays reuse device-global state).
__global__ void k_init() {
    int j = blockIdx.x * blockDim.x + threadIdx.x;
    g_b[j] = __expf(g_cmax[j]);
    if (j < NBLK) g_flags[j] = 0u;
}

// ---------------------------------------------------------------------------
// Persistent Sinkhorn loop. 256 blocks x 256 threads, 2 blocks/SM.
//   Phase A (block owns 4 rows):  a_i = mu_i / (K[i,:].b)
//     rows 0-1 via __ldg  -> 64 KB/block stays L1-resident across iterations
//     rows 2-3 via __ldcg -> streamed from L2 (no L1 pollution)
//   Phase B (block owns 32 cols): b_j = s*nu_j / (K[:,j].a)   [all .cg]
__global__ void __launch_bounds__(NTHR, 2) k_loop(const float* __restrict__ att) {
    int bid = blockIdx.x, tid = threadIdx.x;
    __shared__ float a_sh[M_Q];
    __shared__ float red[4][9];
    __shared__ float redB[32][33];
    int i0 = bid * 4;
    int lane = tid & 31, warp = tid >> 5;
    const float sc = g_s;

    for (int it = 0; it < OT_ITERS; ++it) {
        // ---- Phase A ----
        {
            const float4* Kr = (const float4*)(g_K + (size_t)i0 * N_T);
            float acc[4] = {};
#pragma unroll
            for (int s = 0; s < 8; s++) {
                int j4 = tid + s * NTHR;                 // 0..2047
                float4 bb = __ldcg(((const float4*)g_b) + j4);
                float4 k0 = __ldg (Kr + 0 * (N_T / 4) + j4);
                float4 k1 = __ldg (Kr + 1 * (N_T / 4) + j4);
                float4 k2 = __ldcg(Kr + 2 * (N_T / 4) + j4);
                float4 k3 = __ldcg(Kr + 3 * (N_T / 4) + j4);
                acc[0] += k0.x * bb.x + k0.y * bb.y + k0.z * bb.z + k0.w * bb.w;
                acc[1] += k1.x * bb.x + k1.y * bb.y + k1.z * bb.z + k1.w * bb.w;
                acc[2] += k2.x * bb.x + k2.y * bb.y + k2.z * bb.z + k2.w * bb.w;
                acc[3] += k3.x * bb.x + k3.y * bb.y + k3.z * bb.z + k3.w * bb.w;
            }
#pragma unroll
            for (int r = 0; r < 4; r++) {
                float v = acc[r];
                v += __shfl_xor_sync(0xffffffffu, v, 16);
                v += __shfl_xor_sync(0xffffffffu, v, 8);
                v += __shfl_xor_sync(0xffffffffu, v, 4);
                v += __shfl_xor_sync(0xffffffffu, v, 2);
                v += __shfl_xor_sync(0xffffffffu, v, 1);
                if (lane == 0) red[r][warp] = v;
            }
            __syncthreads();
            if (tid < 4) {
                float s = 0.f;
#pragma unroll
                for (int w = 0; w < 8; w++) s += red[tid][w];
                __stcg(&g_a[i0 + tid], att[i0 + tid] / fmaxf(s, 1e-35f));
            }
        }
        grid_bar(2 * it + 1);

        // ---- Phase B ----
        {
            for (int i = tid; i < M_Q; i += NTHR) a_sh[i] = __ldcg(&g_a[i]);
            __syncthreads();
            int cg = tid & 7;          // 8 col-groups of 4 cols (one float4)
            int rg = tid >> 3;         // 32 row-groups of 32 rows
            const float4* Kc = (const float4*)(g_K + (size_t)(rg * 32) * N_T + bid * 32) + cg;
            const float* av = a_sh + rg * 32;
            float acc[4] = {};
#pragma unroll 8
            for (int r = 0; r < 32; r++) {
                float4 k = __ldcg(Kc + (size_t)r * (N_T / 4));
                float a = av[r];
                acc[0] += k.x * a; acc[1] += k.y * a;
                acc[2] += k.z * a; acc[3] += k.w * a;
            }
#pragma unroll
            for (int c = 0; c < 4; c++) redB[rg][cg * 4 + c] = acc[c];
            __syncthreads();
            if (tid < 32) {
                float s = 0.f;
#pragma unroll
                for (int r = 0; r < 32; r++) s += redB[r][tid];
                __stcg(&g_b[bid * 32 + tid],
                       sc * att[M_Q + bid * 32 + tid] / fmaxf(s, 1e-35f));
            }
        }
        grid_bar(2 * it + 2);
    }
}

// ---------------------------------------------------------------------------
// Epilogue GEMM: R[i][c] = inv_s * a_i * sum_j K[i][j]*b_j * T[j][c]
__global__ void k_pt(const float* __restrict__ x) {
    __shared__ float Ks[64][68];
    __shared__ float Ts[64][68];
    int c0 = blockIdx.x * 64;
    int i0 = blockIdx.y * 64;
    int tx = threadIdx.x, ty = threadIdx.y;
    int t = ty * 16 + tx;
    float acc[4][4] = {};
    for (int jt = 0; jt < N_T / 64; jt++) {
        int j0 = jt * 64;
        int img = j0 >> 10, p0 = j0 & 1023;
        const float* Tbase = x + (size_t)(img + 1) * CDIM * 1024;
#pragma unroll
        for (int s = 0; s < 16; s++) {
            int e = t + s * 256;
            int jj = e & 63, r = e >> 6;
            Ks[jj][r] = g_K[(size_t)(i0 + r) * N_T + j0 + jj] * g_b[j0 + jj];
            Ts[jj][r] = Tbase[(size_t)(c0 + r) * 1024 + p0 + jj];
        }
        __syncthreads();
#pragma unroll
        for (int jj = 0; jj < 64; jj++) {
            float4 ra = *(const float4*)&Ks[jj][ty * 4];
            float4 rb = *(const float4*)&Ts[jj][tx * 4];
            acc[0][0] += ra.x * rb.x; acc[0][1] += ra.x * rb.y; acc[0][2] += ra.x * rb.z; acc[0][3] += ra.x * rb.w;
            acc[1][0] += ra.y * rb.x; acc[1][1] += ra.y * rb.y; acc[1][2] += ra.y * rb.z; acc[1][3] += ra.y * rb.w;
            acc[2][0] += ra.z * rb.x; acc[2][1] += ra.z * rb.y; acc[2][2] += ra.z * rb.z; acc[2][3] += ra.z * rb.w;
            acc[3][0] += ra.w * rb.x; acc[3][1] += ra.w * rb.y; acc[3][2] += ra.w * rb.z; acc[3][3] += ra.w * rb.w;
        }
        __syncthreads();
    }
    float inv = g_inv_s;
#pragma unroll
    for (int u = 0; u < 4; u++) {
        int i = i0 + ty * 4 + u;
        float a = g_a[i] * inv;
#pragma unroll
        for (int v = 0; v < 4; v++)
            g_R[(size_t)i * CDIM + c0 + tx * 4 + v] = a * acc[u][v];
    }
}

__global__ void k_norm(const float* __restrict__ x, const float* __restrict__ att) {
    int i = blockIdx.x;
    int c = threadIdx.x;
    float mu = att[i];
    float q = x[(size_t)c * 1024 + i];
    float d = mu * q - g_R[(size_t)i * CDIM + c];
    __shared__ float sm[256];
    sm[c] = d * d; __syncthreads();
    for (int s = 128; s > 0; s >>= 1) {
        if (c < s) sm[c] += sm[c + s];
        __syncthreads();
    }
    if (c == 0) g_rn[i] = sqrtf(sm[0]);
}

__global__ void k_final(const int* __restrict__ label, float* __restrict__ out) {
    __shared__ float sm[1024];
    int tid = threadIdx.x;
    sm[tid] = g_rn[tid]; __syncthreads();
    for (int s = 512; s > 0; s >>= 1) {
        if (tid < s) sm[tid] += sm[tid + s];
        __syncthreads();
    }
    if (tid == 0) {
        float d = sm[0];
        out[0] = (*label) ? d : fmaxf(MARGIN_V - d, 0.f);
    }
}

// ---------------------------------------------------------------------------
extern "C" void kernel_launch(void* const* d_in, const int* in_sizes, int n_in,
                              void* d_out, int out_size) {
    const float* x     = (const float*)d_in[0];
    const float* att   = (const float*)d_in[1];
    const int*   label = (const int*)d_in[2];
    float* out = (float*)d_out;

    // Setup
    k_t<<<32, 256>>>(x);
    k_gemm<<<dim3(N_T / 64, M_Q / 64), dim3(16, 16)>>>(x);
    k_rmax<<<M_Q, 256>>>();
    k_cmax<<<N_T / 256, 256>>>();
    k_exp<<<M_Q, 256>>>();
    k_sums<<<1, 256>>>(att);
    k_init<<<32, 256>>>();

    // Entire 1000-iteration Sinkhorn loop in ONE persistent kernel
    k_loop<<<NBLK, NTHR>>>(att);

    // Epilogue
    k_pt<<<dim3(CDIM / 64, M_Q / 64), dim3(16, 16)>>>(x);
    k_norm<<<M_Q, 256>>>(x, att);
    k_final<<<1, 1024>>>(label, out);
}

// round 8
// speedup vs baseline: 2.3161x; 2.3161x over previous
#include <cuda_runtime.h>
#include <cuda_fp16.h>

#define M_Q   1024
#define N_T   8192
#define CDIM  256
#define OT_ITERS 1000
#define MARGIN_V 0.7f
#define NBLK 128
#define NTHR 512

// Static scratch (no runtime allocation allowed)
__device__ __align__(256) float g_K[M_Q * N_T];   // fp32 kernel matrix (32 MB)
__device__ __align__(256) float g_a[M_Q];
__device__ __align__(256) float g_b[N_T];
__device__ float  g_t[N_T];
__device__ float  g_rmax[M_Q];
__device__ float  g_cmax[N_T];
__device__ float  g_cpart[8 * N_T];
__device__ float  g_R[M_Q * CDIM];
__device__ float  g_rn[M_Q];
__device__ float  g_s;                // Smu/Snu  (per-iter scale folded into nu)
__device__ float  g_inv_s;            // Snu/Smu  (epilogue correction)

// Proven grid barrier (R4): atomicInc + volatile generation counter.
// Only tid0 of each block spins; the rest park at bar.sync.
__device__ volatile unsigned g_bar_gen;
__device__ unsigned g_bar_cnt;

__device__ __forceinline__ void grid_bar() {
    __syncthreads();
    if (threadIdx.x == 0) {
        __threadfence();
        unsigned gen = g_bar_gen;
        unsigned old = atomicInc(&g_bar_cnt, NBLK - 1);
        if (old == NBLK - 1) {
            __threadfence();
            g_bar_gen = gen + 1;
        } else {
            while (g_bar_gen == gen) __nanosleep(64);
        }
    }
    __syncthreads();
}

// ---------------------------------------------------------------------------
// t_j = sum_c T[j][c]^2
__global__ void k_t(const float* __restrict__ x) {
    int j = blockIdx.x * blockDim.x + threadIdx.x;
    int img = j >> 10, p = j & 1023;
    const float* base = x + (size_t)(img + 1) * CDIM * 1024 + p;
    float s = 0.f;
#pragma unroll 8
    for (int c = 0; c < CDIM; c++) { float v = base[c * 1024]; s += v * v; }
    g_t[j] = s;
}

// D[i][j] = t_j - 2 * sum_c Q[i][c]*T[j][c]   (fp32, into g_K)
__global__ void k_gemm(const float* __restrict__ x) {
    __shared__ float As[16][64];
    __shared__ float Bs[16][64];
    int i0 = blockIdx.y * 64;
    int j0 = blockIdx.x * 64;
    int img = j0 >> 10, p0 = j0 & 1023;
    const float* A = x;
    const float* B = x + (size_t)(img + 1) * CDIM * 1024;
    int tx = threadIdx.x, ty = threadIdx.y;
    int t = ty * 16 + tx;
    float acc[4][4] = {};
    for (int k0 = 0; k0 < CDIM; k0 += 16) {
#pragma unroll
        for (int s = 0; s < 4; s++) {
            int e = t + s * 256;
            int cl = e >> 6, il = e & 63;
            As[cl][il] = A[(size_t)(k0 + cl) * 1024 + i0 + il];
            Bs[cl][il] = B[(size_t)(k0 + cl) * 1024 + p0 + il];
        }
        __syncthreads();
#pragma unroll
        for (int c = 0; c < 16; c++) {
            float ra[4], rb[4];
#pragma unroll
            for (int u = 0; u < 4; u++) ra[u] = As[c][ty * 4 + u];
#pragma unroll
            for (int v = 0; v < 4; v++) rb[v] = Bs[c][tx * 4 + v];
#pragma unroll
            for (int u = 0; u < 4; u++)
#pragma unroll
                for (int v = 0; v < 4; v++) acc[u][v] += ra[u] * rb[v];
        }
        __syncthreads();
    }
#pragma unroll
    for (int u = 0; u < 4; u++) {
        int i = i0 + ty * 4 + u;
#pragma unroll
        for (int v = 0; v < 4; v++) {
            int j = j0 + tx * 4 + v;
            g_K[(size_t)i * N_T + j] = g_t[j] - 2.f * acc[u][v];
        }
    }
}

__global__ void k_rmax() {
    int i = blockIdx.x;
    const float* row = g_K + (size_t)i * N_T;
    int tid = threadIdx.x;
    float m = -1e30f;
    for (int j = tid; j < N_T; j += 256) m = fmaxf(m, row[j]);
    __shared__ float sm[256];
    sm[tid] = m; __syncthreads();
    for (int s = 128; s > 0; s >>= 1) {
        if (tid < s) sm[tid] = fmaxf(sm[tid], sm[tid + s]);
        __syncthreads();
    }
    if (tid == 0) g_rmax[i] = sm[0];
}

// Column max of (D - rmax), stage 1: 8 row-chunks of 128 rows
__global__ void k_cmax1() {
    int j = blockIdx.x * 256 + threadIdx.x;
    int i0 = blockIdx.y * 128;
    float m = -1e30f;
    for (int i = i0; i < i0 + 128; i++)
        m = fmaxf(m, g_K[(size_t)i * N_T + j] - g_rmax[i]);
    g_cpart[blockIdx.y * N_T + j] = m;
}
// stage 2: combine
__global__ void k_cmax2() {
    int j = blockIdx.x * 256 + threadIdx.x;
    float m = -1e30f;
#pragma unroll
    for (int c = 0; c < 8; c++) m = fmaxf(m, g_cpart[c * N_T + j]);
    g_cmax[j] = m;
}

// K = exp(D - rmax_i - cmax_j) in place (fp32 — proven numerics).
__global__ void k_exp() {
    int i = blockIdx.x;
    float* row = g_K + (size_t)i * N_T;
    float rm = g_rmax[i];
    for (int j = threadIdx.x; j < N_T; j += 256)
        row[j] = __expf(row[j] - rm - g_cmax[j]);
}

// Marginal sums -> per-iteration scale s = Smu/Snu (exact drift kill)
__global__ void k_sums(const float* __restrict__ att) {
    __shared__ float sm[256];
    int tid = threadIdx.x;
    float s1 = 0.f;
    for (int i = tid; i < M_Q; i += 256) s1 += att[i];
    sm[tid] = s1; __syncthreads();
    for (int s = 128; s > 0; s >>= 1) { if (tid < s) sm[tid] += sm[tid + s]; __syncthreads(); }
    float smu = sm[0]; __syncthreads();
    float s2 = 0.f;
    for (int j = tid; j < N_T; j += 256) s2 += att[M_Q + j];
    sm[tid] = s2; __syncthreads();
    for (int s = 128; s > 0; s >>= 1) { if (tid < s) sm[tid] += sm[tid + s]; __syncthreads(); }
    if (tid == 0) { g_s = smu / sm[0]; g_inv_s = sm[0] / smu; }
}

// b_0 = exp(cmax_j)  (== reference v=0 start); reset barrier state
__global__ void k_init() {
    int j = blockIdx.x * blockDim.x + threadIdx.x;
    g_b[j] = __expf(g_cmax[j]);
    if (j == 0) { g_bar_cnt = 0; g_bar_gen = 0; }
}

// ---------------------------------------------------------------------------
// Persistent Sinkhorn loop: 128 blocks x 512 threads (16 warps/SM, 1 blk/SM).
//   Phase A (block owns 8 rows):  a_i = mu_i / (K[i,:].b)
//     rows 0-3 via __ldg  -> 128 KB L1-resident across iterations
//     rows 4-7 via __ldcg -> streamed from L2
//   Phase B (block owns 64 cols): b_j = s*nu_j / (K[:,j].a)   [all .cg]
__global__ void __launch_bounds__(NTHR, 1) k_loop(const float* __restrict__ att) {
    int bid = blockIdx.x, tid = threadIdx.x;
    __shared__ float a_sh[M_Q];
    __shared__ float red[8][17];
    __shared__ float redB[32][68];
    int i0 = bid * 8;
    int lane = tid & 31, warp = tid >> 5;
    const float sc = g_s;

    for (int it = 0; it < OT_ITERS; ++it) {
        // ---- Phase A ----
        {
            const float4* Kr = (const float4*)(g_K + (size_t)i0 * N_T);
            float acc[8] = {};
#pragma unroll
            for (int s = 0; s < 4; s++) {
                int j4 = tid + s * NTHR;                 // 0..2047
                float4 bb = __ldcg(((const float4*)g_b) + j4);
#pragma unroll
                for (int r = 0; r < 8; r++) {
                    float4 k = (r < 4) ? __ldg(Kr + (size_t)r * (N_T / 4) + j4)
                                       : __ldcg(Kr + (size_t)r * (N_T / 4) + j4);
                    acc[r] += k.x * bb.x + k.y * bb.y + k.z * bb.z + k.w * bb.w;
                }
            }
#pragma unroll
            for (int r = 0; r < 8; r++) {
                float v = acc[r];
                v += __shfl_xor_sync(0xffffffffu, v, 16);
                v += __shfl_xor_sync(0xffffffffu, v, 8);
                v += __shfl_xor_sync(0xffffffffu, v, 4);
                v += __shfl_xor_sync(0xffffffffu, v, 2);
                v += __shfl_xor_sync(0xffffffffu, v, 1);
                if (lane == 0) red[r][warp] = v;
            }
            __syncthreads();
            if (tid < 8) {
                float s = 0.f;
#pragma unroll
                for (int w = 0; w < 16; w++) s += red[tid][w];
                __stcg(&g_a[i0 + tid], att[i0 + tid] / fmaxf(s, 1e-35f));
            }
        }
        grid_bar();

        // ---- Phase B ----
        {
            for (int i = tid; i < M_Q; i += NTHR) a_sh[i] = __ldcg(&g_a[i]);
            __syncthreads();
            int cg = tid & 15;         // 16 float4 col-groups = 64 cols
            int rg = tid >> 4;         // 32 row-groups of 32 rows
            const float4* Kc = (const float4*)(g_K + (size_t)(rg * 32) * N_T + bid * 64) + cg;
            const float* av = a_sh + rg * 32;
            float acc[4] = {};
#pragma unroll 8
            for (int r = 0; r < 32; r++) {
                float4 k = __ldcg(Kc + (size_t)r * (N_T / 4));
                float a = av[r];
                acc[0] += k.x * a; acc[1] += k.y * a;
                acc[2] += k.z * a; acc[3] += k.w * a;
            }
#pragma unroll
            for (int c = 0; c < 4; c++) redB[rg][cg * 4 + c] = acc[c];
            __syncthreads();
            if (tid < 64) {
                float s = 0.f;
#pragma unroll
                for (int r = 0; r < 32; r++) s += redB[r][tid];
                __stcg(&g_b[bid * 64 + tid],
                       sc * att[M_Q + bid * 64 + tid] / fmaxf(s, 1e-35f));
            }
        }
        grid_bar();
    }
}

// ---------------------------------------------------------------------------
// Epilogue GEMM: R[i][c] = inv_s * a_i * sum_j K[i][j]*b_j * T[j][c]
__global__ void k_pt(const float* __restrict__ x) {
    __shared__ float Ks[64][68];
    __shared__ float Ts[64][68];
    int c0 = blockIdx.x * 64;
    int i0 = blockIdx.y * 64;
    int tx = threadIdx.x, ty = threadIdx.y;
    int t = ty * 16 + tx;
    float acc[4][4] = {};
    for (int jt = 0; jt < N_T / 64; jt++) {
        int j0 = jt * 64;
        int img = j0 >> 10, p0 = j0 & 1023;
        const float* Tbase = x + (size_t)(img + 1) * CDIM * 1024;
#pragma unroll
        for (int s = 0; s < 16; s++) {
            int e = t + s * 256;
            int jj = e & 63, r = e >> 6;
            Ks[jj][r] = g_K[(size_t)(i0 + r) * N_T + j0 + jj] * g_b[j0 + jj];
            Ts[jj][r] = Tbase[(size_t)(c0 + r) * 1024 + p0 + jj];
        }
        __syncthreads();
#pragma unroll
        for (int jj = 0; jj < 64; jj++) {
            float4 ra = *(const float4*)&Ks[jj][ty * 4];
            float4 rb = *(const float4*)&Ts[jj][tx * 4];
            acc[0][0] += ra.x * rb.x; acc[0][1] += ra.x * rb.y; acc[0][2] += ra.x * rb.z; acc[0][3] += ra.x * rb.w;
            acc[1][0] += ra.y * rb.x; acc[1][1] += ra.y * rb.y; acc[1][2] += ra.y * rb.z; acc[1][3] += ra.y * rb.w;
            acc[2][0] += ra.z * rb.x; acc[2][1] += ra.z * rb.y; acc[2][2] += ra.z * rb.z; acc[2][3] += ra.z * rb.w;
            acc[3][0] += ra.w * rb.x; acc[3][1] += ra.w * rb.y; acc[3][2] += ra.w * rb.z; acc[3][3] += ra.w * rb.w;
        }
        __syncthreads();
    }
    float inv = g_inv_s;
#pragma unroll
    for (int u = 0; u < 4; u++) {
        int i = i0 + ty * 4 + u;
        float a = g_a[i] * inv;
#pragma unroll
        for (int v = 0; v < 4; v++)
            g_R[(size_t)i * CDIM + c0 + tx * 4 + v] = a * acc[u][v];
    }
}

__global__ void k_norm(const float* __restrict__ x, const float* __restrict__ att) {
    int i = blockIdx.x;
    int c = threadIdx.x;
    float mu = att[i];
    float q = x[(size_t)c * 1024 + i];
    float d = mu * q - g_R[(size_t)i * CDIM + c];
    __shared__ float sm[256];
    sm[c] = d * d; __syncthreads();
    for (int s = 128; s > 0; s >>= 1) {
        if (c < s) sm[c] += sm[c + s];
        __syncthreads();
    }
    if (c == 0) g_rn[i] = sqrtf(sm[0]);
}

__global__ void k_final(const int* __restrict__ label, float* __restrict__ out) {
    __shared__ float sm[1024];
    int tid = threadIdx.x;
    sm[tid] = g_rn[tid]; __syncthreads();
    for (int s = 512; s > 0; s >>= 1) {
        if (tid < s) sm[tid] += sm[tid + s];
        __syncthreads();
    }
    if (tid == 0) {
        float d = sm[0];
        out[0] = (*label) ? d : fmaxf(MARGIN_V - d, 0.f);
    }
}

// ---------------------------------------------------------------------------
extern "C" void kernel_launch(void* const* d_in, const int* in_sizes, int n_in,
                              void* d_out, int out_size) {
    const float* x     = (const float*)d_in[0];
    const float* att   = (const float*)d_in[1];
    const int*   label = (const int*)d_in[2];
    float* out = (float*)d_out;

    // Setup
    k_t<<<32, 256>>>(x);
    k_gemm<<<dim3(N_T / 64, M_Q / 64), dim3(16, 16)>>>(x);
    k_rmax<<<M_Q, 256>>>();
    k_cmax1<<<dim3(32, 8), 256>>>();
    k_cmax2<<<32, 256>>>();
    k_exp<<<M_Q, 256>>>();
    k_sums<<<1, 256>>>(att);
    k_init<<<32, 256>>>();

    // Entire 1000-iteration Sinkhorn loop in ONE persistent kernel
    k_loop<<<NBLK, NTHR>>>(att);

    // Epilogue
    k_pt<<<dim3(CDIM / 64, M_Q / 64), dim3(16, 16)>>>(x);
    k_norm<<<M_Q, 256>>>(x, att);
    k_final<<<1, 1024>>>(label, out);
}